// round 6
// baseline (speedup 1.0000x reference)
#include <cuda_runtime.h>
#include <cstdint>

#define Tn 168
#define Pn 16
#define Hn 24
#define Gn 96
#define Bn 8192
#define NTHREADS 224          // 7 warps
#define En 8                  // elements per warp
#define EPC 56                // 7*8
#define NR 48                 // padded reduction rows: x16 + h24 + pad8
#define VS 52                 // v row stride (floats); 52 mod 32 = 20 -> good bank spread

typedef unsigned long long ull;

// ---- packed f32x2 helpers ----
__device__ __forceinline__ ull pk2(float lo, float hi) {
    ull r; asm("mov.b64 %0, {%1, %2};" : "=l"(r) : "f"(lo), "f"(hi)); return r;
}
__device__ __forceinline__ void fma2(ull& d, ull a, ull b) {
    asm("fma.rn.f32x2 %0, %1, %2, %0;" : "+l"(d) : "l"(a), "l"(b));
}
__device__ __forceinline__ void add2(ull& d, ull a) {
    asm("add.rn.f32x2 %0, %0, %1;" : "+l"(d) : "l"(a));
}
__device__ __forceinline__ void unpk2(ull v, float& lo, float& hi) {
    asm("mov.b64 {%0, %1}, %2;" : "=f"(lo), "=f"(hi) : "l"(v));
}
__device__ __forceinline__ float tanhapx(float x) {
    float y; asm("tanh.approx.f32 %0, %1;" : "=f"(y) : "f"(x)); return y;
}
__device__ __forceinline__ ull shfl_xor64(ull v, int m) {
    uint2 u; asm("mov.b64 {%0, %1}, %2;" : "=r"(u.x), "=r"(u.y) : "l"(v));
    u.x = __shfl_xor_sync(0xffffffffu, u.x, m);
    u.y = __shfl_xor_sync(0xffffffffu, u.y, m);
    ull r; asm("mov.b64 %0, {%1, %2};" : "=l"(r) : "r"(u.x), "r"(u.y));
    return r;
}

__global__ __launch_bounds__(NTHREADS, 1)
void lstm_fused_kernel(const float* __restrict__ x,
                       const float* __restrict__ Wih,   // [96,16]
                       const float* __restrict__ Whh,   // [96,24]
                       const float* __restrict__ bih,   // [96]
                       const float* __restrict__ bhh,   // [96]
                       const float* __restrict__ Wlin,  // [24,24]
                       const float* __restrict__ blin,  // [24]
                       float* __restrict__ out)         // [8192,24]
{
    // Combined weight matrix sW[NR][96], rows 0-15 = Wih, 16-39 = Whh, 40-47 = 0.
    // Columns owner-major: gate (type tt, unit j) -> col (j/3)*12 + tt*3 + j%3.
    // i/f/o pre-scaled by 0.5 (sigmoid(v) = 0.5*tanh(0.5v)+0.5).
    __shared__ float sW[NR * Gn];        // staged once, then register-cached
    __shared__ float sV[EPC * VS];       // per element: [0:16)=x(t), [16:40)=h, [40:48)=0
    __shared__ float sWlin[Hn * Hn];     // [j][m]
    __shared__ float sBlin[Hn];

    const int tid = threadIdx.x;
    const int wid = tid >> 5;
    const int l32 = tid & 31;
    const int kq  = l32 >> 3;            // row-quarter (12 rows)
    const int l8  = l32 & 7;             // gate owner (12 cols)
    const int el0 = wid * En;            // warp-private element window
    const int eg0 = blockIdx.x * EPC + el0;
    const int j0  = l8 * 3;
    const int exl = l32 >> 2;            // x-staging element (0..7)
    const int q4  = l32 & 3;             // x-staging quarter
    const int egx = eg0 - el0 + ((blockIdx.x * EPC + el0) - eg0) + eg0 + exl - eg0; // = eg0+exl
    const int egx2 = eg0 + exl;

    // ---- prologue ----
    for (int i = tid; i < NR * Gn; i += NTHREADS) sW[i] = 0.0f;
    for (int i = tid; i < EPC * VS; i += NTHREADS) sV[i] = 0.0f;
    __syncthreads();

    for (int i = tid; i < Pn * Gn; i += NTHREADS) {
        int g = i >> 4, p = i & 15;
        int tt = g / Hn, j = g - tt * Hn;
        int own = (j / 3) * 12 + tt * 3 + (j % 3);
        float sc = (tt == 2) ? 1.0f : 0.5f;
        sW[p * Gn + own] = Wih[i] * sc;
    }
    for (int i = tid; i < Gn * Hn; i += NTHREADS) {
        int g = i / Hn, k = i - g * Hn;
        int tt = g / Hn, j = g - tt * Hn;
        int own = (j / 3) * 12 + tt * 3 + (j % 3);
        float sc = (tt == 2) ? 1.0f : 0.5f;
        sW[(16 + k) * Gn + own] = Whh[i] * sc;
    }
    for (int i = tid; i < Hn * Hn; i += NTHREADS) {
        int m = i / Hn, j = i - m * Hn;
        sWlin[j * Hn + m] = Wlin[i];
    }
    for (int i = tid; i < Hn; i += NTHREADS) sBlin[i] = blin[i];

    // x(t=0): lane stages one float4 of its warp's element exl
    if (egx2 < Bn) {
        float4 v = *reinterpret_cast<const float4*>(&x[(size_t)egx2 * (Tn * Pn) + q4 * 4]);
        *reinterpret_cast<float4*>(&sV[(el0 + exl) * VS + q4 * 4]) = v;
    }
    __syncthreads();

    // register-cache this lane's weight slice: rows [12kq,12kq+12) x cols [12l8,12l8+12)
    ull w[12][6];
#pragma unroll
    for (int r = 0; r < 12; r++) {
        const ulonglong2* wp = reinterpret_cast<const ulonglong2*>(
            &sW[(kq * 12 + r) * Gn + l8 * 12]);
        ulonglong2 a = wp[0], b = wp[1], cc = wp[2];
        w[r][0] = a.x; w[r][1] = a.y; w[r][2] = b.x;
        w[r][3] = b.y; w[r][4] = cc.x; w[r][5] = cc.y;
    }

    // bias only on kq==0 lanes (counted once in the cross-quarter sum)
    ull bias[6];
    {
        float bv[12];
#pragma unroll
        for (int q = 0; q < 12; q++) {
            int tt = q / 3;
            int g = tt * Hn + j0 + (q - tt * 3);
            float sc = (tt == 2) ? 1.0f : 0.5f;
            bv[q] = (kq == 0) ? (bih[g] + bhh[g]) * sc : 0.0f;
        }
#pragma unroll
        for (int s = 0; s < 6; s++) bias[s] = pk2(bv[2 * s], bv[2 * s + 1]);
    }

    float c[2][3] = {{0, 0, 0}, {0, 0, 0}};   // cell state for owned elems {kq, 4+kq}

    for (int t = 0; t < Tn; t++) {
        // prefetch x(t+1) early (hidden under compute)
        float4 xpf = make_float4(0.f, 0.f, 0.f, 0.f);
        if (t + 1 < Tn && egx2 < Bn)
            xpf = *reinterpret_cast<const float4*>(
                &x[(size_t)egx2 * (Tn * Pn) + (t + 1) * Pn + q4 * 4]);

#pragma unroll
        for (int b = 0; b < 2; b++) {
            ull acc[4][6];
#pragma unroll
            for (int e4 = 0; e4 < 4; e4++) {
                const int e = b * 4 + e4;
                const float4* vv = reinterpret_cast<const float4*>(
                    &sV[(el0 + e) * VS + kq * 12]);
                float4 a0 = vv[0], a1 = vv[1], a2 = vv[2];
                float vr[12] = {a0.x, a0.y, a0.z, a0.w,
                                a1.x, a1.y, a1.z, a1.w,
                                a2.x, a2.y, a2.z, a2.w};
#pragma unroll
                for (int s = 0; s < 6; s++) acc[e4][s] = bias[s];
#pragma unroll
                for (int r = 0; r < 12; r++) {
                    ull vs = pk2(vr[r], vr[r]);
                    fma2(acc[e4][0], vs, w[r][0]);
                    fma2(acc[e4][1], vs, w[r][1]);
                    fma2(acc[e4][2], vs, w[r][2]);
                    fma2(acc[e4][3], vs, w[r][3]);
                    fma2(acc[e4][4], vs, w[r][4]);
                    fma2(acc[e4][5], vs, w[r][5]);
                }
            }
            // cross-quarter butterfly (xor 8, xor 16): full 48-row sums on all lanes
#pragma unroll
            for (int e4 = 0; e4 < 4; e4++)
#pragma unroll
                for (int s = 0; s < 6; s++) {
                    add2(acc[e4][s], shfl_xor64(acc[e4][s], 8));
                    add2(acc[e4][s], shfl_xor64(acc[e4][s], 16));
                }
            // this lane's element: e_own = b*4 + kq -> select acc[kq]
            float v12[12];
#pragma unroll
            for (int s = 0; s < 6; s++) {
                ull g = (kq == 0) ? acc[0][s] : (kq == 1) ? acc[1][s]
                       : (kq == 2) ? acc[2][s] : acc[3][s];
                unpk2(g, v12[2 * s], v12[2 * s + 1]);
            }
#pragma unroll
            for (int q = 0; q < 3; q++) {
                float iv = fmaf(tanhapx(v12[q]),     0.5f, 0.5f);
                float fv = fmaf(tanhapx(v12[3 + q]), 0.5f, 0.5f);
                float gv = tanhapx(v12[6 + q]);
                float ov = fmaf(tanhapx(v12[9 + q]), 0.5f, 0.5f);
                c[b][q] = fv * c[b][q] + iv * gv;
                float hval = ov * tanhapx(c[b][q]);
                sV[(el0 + b * 4 + kq) * VS + 16 + j0 + q] = hval;
            }
        }

        // stage x(t+1) (single buffer; safe: all x reads done before batch-1 shfl)
        *reinterpret_cast<float4*>(&sV[(el0 + exl) * VS + q4 * 4]) = xpf;

        __syncwarp();
    }

    // ---- epilogue: out = tanh(h_last) @ Wlin^T + blin (warp-private) ----
    // tanh in place: lane handles element exl, h-indices q4*6..q4*6+6
#pragma unroll
    for (int n = 0; n < 6; n++) {
        int a = (el0 + exl) * VS + 16 + q4 * 6 + n;
        sV[a] = tanhapx(sV[a]);
    }
    __syncwarp();

    {
#pragma unroll
        for (int n = 0; n < 6; n++) {
            int m = q4 * 6 + n;
            float a = sBlin[m];
            const float* th = &sV[(el0 + exl) * VS + 16];
#pragma unroll
            for (int j = 0; j < Hn; j++)
                a += th[j] * sWlin[j * Hn + m];
            if (egx2 < Bn) out[(size_t)egx2 * Hn + m] = a;
        }
    }
}

extern "C" void kernel_launch(void* const* d_in, const int* in_sizes, int n_in,
                              void* d_out, int out_size) {
    const float* x    = (const float*)d_in[0];
    const float* Wih  = (const float*)d_in[1];
    const float* Whh  = (const float*)d_in[2];
    const float* bih  = (const float*)d_in[3];
    const float* bhh  = (const float*)d_in[4];
    const float* Wlin = (const float*)d_in[5];
    const float* blin = (const float*)d_in[6];
    float* out = (float*)d_out;

    const int grid = (Bn + EPC - 1) / EPC;  // 147 -> 1 CTA per SM
    lstm_fused_kernel<<<grid, NTHREADS>>>(x, Wih, Whh, bih, bhh, Wlin, blin, out);
}

// round 7
// speedup vs baseline: 1.5363x; 1.5363x over previous
#include <cuda_runtime.h>
#include <cstdint>

#define Tn 168
#define Pn 16
#define Hn 24
#define Gn 96
#define Bn 8192
#define NTHREADS 224          // 7 warps
#define En 8                  // elements per warp
#define EPC 56
#define WS 96                 // sW row stride (floats)
#define VS 44                 // sV row stride: [0:16)=x, [16:40)=h, [40:44) pad

typedef unsigned long long ull;

__device__ __forceinline__ ull pk2s(float v) {
    ull r; asm("mov.b64 %0, {%1, %1};" : "=l"(r) : "f"(v)); return r;
}
__device__ __forceinline__ ull pk2(float lo, float hi) {
    ull r; asm("mov.b64 %0, {%1, %2};" : "=l"(r) : "f"(lo), "f"(hi)); return r;
}
__device__ __forceinline__ void fma2(ull& d, ull a, ull b) {
    asm("fma.rn.f32x2 %0, %1, %2, %0;" : "+l"(d) : "l"(a), "l"(b));
}
__device__ __forceinline__ ull add2r(ull a, ull b) {
    ull d; asm("add.rn.f32x2 %0, %1, %2;" : "=l"(d) : "l"(a), "l"(b)); return d;
}
__device__ __forceinline__ void unpk2(ull v, float& lo, float& hi) {
    asm("mov.b64 {%0, %1}, %2;" : "=f"(lo), "=f"(hi) : "l"(v));
}
__device__ __forceinline__ float tanhapx(float x) {
    float y; asm("tanh.approx.f32 %0, %1;" : "=f"(y) : "f"(x)); return y;
}
__device__ __forceinline__ ull shfl_xor64(ull v, int m) {
    uint2 u; asm("mov.b64 {%0, %1}, %2;" : "=r"(u.x), "=r"(u.y) : "l"(v));
    u.x = __shfl_xor_sync(0xffffffffu, u.x, m);
    u.y = __shfl_xor_sync(0xffffffffu, u.y, m);
    ull r; asm("mov.b64 %0, {%1, %2};" : "=l"(r) : "r"(u.x), "r"(u.y));
    return r;
}

__global__ __launch_bounds__(NTHREADS, 1)
void lstm_fused_kernel(const float* __restrict__ x,
                       const float* __restrict__ Wih,   // [96,16]
                       const float* __restrict__ Whh,   // [96,24]
                       const float* __restrict__ bih,   // [96]
                       const float* __restrict__ bhh,   // [96]
                       const float* __restrict__ Wlin,  // [24,24]
                       const float* __restrict__ blin,  // [24]
                       float* __restrict__ out)         // [8192,24]
{
    // sW[40][96]: rows 0-15 = Wih, 16-39 = Whh. Owner-major cols:
    // gate (type tt, unit j) -> col (j/3)*12 + tt*3 + j%3; i/f/o pre-scaled 0.5
    // (sigmoid(v) = 0.5*tanh(0.5v)+0.5, scale folded into weights+bias).
    __shared__ float sW[40 * WS];
    __shared__ float sV[EPC * VS];       // per elem: 16 x, 24 h, 4 pad
    __shared__ float sWlin[Hn * Hn];     // [j][m]
    __shared__ float sBlin[Hn];

    const int tid = threadIdx.x;
    const int wid = tid >> 5;
    const int l32 = tid & 31;
    const int kq  = l32 >> 3;            // row-quarter: rows [10kq, 10kq+10)
    const int l8  = l32 & 7;             // gate owner: cols [12l8, 12l8+12)
    const int el0 = wid * En;            // warp-private 8-element window
    const int eg0 = blockIdx.x * EPC + el0;
    const int j0  = l8 * 3;
    const int exl = l32 >> 2;            // x-staging element (0..7)
    const int q4  = l32 & 3;             // x-staging quarter
    const int egx = eg0 + exl;

    // ---- prologue ----
    for (int i = tid; i < EPC * VS; i += NTHREADS) sV[i] = 0.0f;
    for (int i = tid; i < Pn * Gn; i += NTHREADS) {
        int g = i >> 4, p = i & 15;
        int tt = g / Hn, j = g - tt * Hn;
        int own = (j / 3) * 12 + tt * 3 + (j % 3);
        float sc = (tt == 2) ? 1.0f : 0.5f;
        sW[p * WS + own] = Wih[i] * sc;
    }
    for (int i = tid; i < Gn * Hn; i += NTHREADS) {
        int g = i / Hn, k = i - g * Hn;
        int tt = g / Hn, j = g - tt * Hn;
        int own = (j / 3) * 12 + tt * 3 + (j % 3);
        float sc = (tt == 2) ? 1.0f : 0.5f;
        sW[(16 + k) * WS + own] = Whh[i] * sc;
    }
    for (int i = tid; i < Hn * Hn; i += NTHREADS) {
        int m = i / Hn, j = i - m * Hn;
        sWlin[j * Hn + m] = Wlin[i];
    }
    for (int i = tid; i < Hn; i += NTHREADS) sBlin[i] = blin[i];

    // bias (counted once: kq==0 lanes only)
    ull bias[6];
    {
        float bv[12];
#pragma unroll
        for (int q = 0; q < 12; q++) {
            int tt = q / 3;
            int g = tt * Hn + j0 + (q - tt * 3);
            float sc = (tt == 2) ? 1.0f : 0.5f;
            bv[q] = (kq == 0) ? (bih[g] + bhh[g]) * sc : 0.0f;
        }
#pragma unroll
        for (int s = 0; s < 6; s++) bias[s] = pk2(bv[2 * s], bv[2 * s + 1]);
    }
    __syncthreads();

    // x(t=0)
    if (egx < Bn) {
        float4 v = *reinterpret_cast<const float4*>(&x[(size_t)egx * (Tn * Pn) + q4 * 4]);
        *reinterpret_cast<float4*>(&sV[(el0 + exl) * VS + q4 * 4]) = v;
    }
    __syncwarp();

    const bool hiq = (kq >= 2);          // round-1 side
    const bool odq = (kq & 1);           // round-2 side
    float c[2][3] = {{0, 0, 0}, {0, 0, 0}};  // cell state for elems {2kq, 2kq+1}

    for (int t = 0; t < Tn; t++) {
        // x(t+1) prefetch (LDG hidden under FMA block)
        float4 xpf = make_float4(0.f, 0.f, 0.f, 0.f);
        if (t + 1 < Tn && egx < Bn)
            xpf = *reinterpret_cast<const float4*>(
                &x[(size_t)egx * (Tn * Pn) + (t + 1) * Pn + q4 * 4]);

        // v slices: rows [10kq, 10kq+10) of [x(16); h(24)] for all 8 elems
        float v[En][10];
#pragma unroll
        for (int e = 0; e < En; e++) {
            const float2* vp = reinterpret_cast<const float2*>(
                &sV[(el0 + e) * VS + kq * 10]);
#pragma unroll
            for (int rr = 0; rr < 5; rr++) {
                float2 d = vp[rr];
                v[e][2 * rr] = d.x; v[e][2 * rr + 1] = d.y;
            }
        }

        // single 8-element FMA block: 48 independent chains
        ull acc[En][6];
#pragma unroll
        for (int e = 0; e < En; e++)
#pragma unroll
            for (int s = 0; s < 6; s++) acc[e][s] = bias[s];

#pragma unroll
        for (int r = 0; r < 10; r++) {
            const ulonglong2* wp = reinterpret_cast<const ulonglong2*>(
                &sW[(kq * 10 + r) * WS + l8 * 12]);
            ulonglong2 wa = wp[0], wb = wp[1], wc = wp[2];
#pragma unroll
            for (int e = 0; e < En; e++) {
                ull vs = pk2s(v[e][r]);
                fma2(acc[e][0], vs, wa.x);
                fma2(acc[e][1], vs, wa.y);
                fma2(acc[e][2], vs, wb.x);
                fma2(acc[e][3], vs, wb.y);
                fma2(acc[e][4], vs, wc.x);
                fma2(acc[e][5], vs, wc.y);
            }
        }

        // reduce-scatter (in place): round 1 over kq-bit1 (lane xor 16)
#pragma unroll
        for (int i = 0; i < 4; i++)
#pragma unroll
            for (int s = 0; s < 6; s++) {
                ull snd = hiq ? acc[i][s] : acc[i + 4][s];
                ull rcv = shfl_xor64(snd, 16);
                ull base = hiq ? acc[i + 4][s] : acc[i][s];
                acc[i][s] = add2r(base, rcv);
            }
        // round 2 over kq-bit0 (lane xor 8): lane ends with elems {2kq, 2kq+1}
#pragma unroll
        for (int i = 0; i < 2; i++)
#pragma unroll
            for (int s = 0; s < 6; s++) {
                ull snd = odq ? acc[i][s] : acc[i + 2][s];
                ull rcv = shfl_xor64(snd, 8);
                ull base = odq ? acc[i + 2][s] : acc[i][s];
                acc[i][s] = add2r(base, rcv);
            }

        // stage x(t+1): safe — shfl above converged all lanes past their v reads
        *reinterpret_cast<float4*>(&sV[(el0 + exl) * VS + q4 * 4]) = xpf;

        // elementwise: this lane owns elems {2kq, 2kq+1}, units j0..j0+2
#pragma unroll
        for (int b = 0; b < 2; b++) {
            const int e = 2 * kq + b;
            float v12[12];
#pragma unroll
            for (int s = 0; s < 6; s++) unpk2(acc[b][s], v12[2 * s], v12[2 * s + 1]);
#pragma unroll
            for (int q = 0; q < 3; q++) {
                float iv = fmaf(tanhapx(v12[q]),     0.5f, 0.5f);
                float fv = fmaf(tanhapx(v12[3 + q]), 0.5f, 0.5f);
                float gv = tanhapx(v12[6 + q]);
                float ov = fmaf(tanhapx(v12[9 + q]), 0.5f, 0.5f);
                c[b][q] = fv * c[b][q] + iv * gv;
                sV[(el0 + e) * VS + 16 + j0 + q] = ov * tanhapx(c[b][q]);
            }
        }

        __syncwarp();   // h(t) + x(t+1) visible for next step's v loads
    }

    // ---- epilogue: out = tanh(h_last) @ Wlin^T + blin (warp-private) ----
#pragma unroll
    for (int n = 0; n < 6; n++) {
        int a = (el0 + exl) * VS + 16 + q4 * 6 + n;
        sV[a] = tanhapx(sV[a]);
    }
    __syncwarp();

#pragma unroll
    for (int n = 0; n < 6; n++) {
        int m = q4 * 6 + n;
        float a = sBlin[m];
        const float* th = &sV[(el0 + exl) * VS + 16];
#pragma unroll
        for (int j = 0; j < Hn; j++)
            a += th[j] * sWlin[j * Hn + m];
        if (egx < Bn) out[(size_t)egx * Hn + m] = a;
    }
}

extern "C" void kernel_launch(void* const* d_in, const int* in_sizes, int n_in,
                              void* d_out, int out_size) {
    const float* x    = (const float*)d_in[0];
    const float* Wih  = (const float*)d_in[1];
    const float* Whh  = (const float*)d_in[2];
    const float* bih  = (const float*)d_in[3];
    const float* bhh  = (const float*)d_in[4];
    const float* Wlin = (const float*)d_in[5];
    const float* blin = (const float*)d_in[6];
    float* out = (float*)d_out;

    const int grid = (Bn + EPC - 1) / EPC;  // 147 -> 1 CTA per SM
    lstm_fused_kernel<<<grid, NTHREADS>>>(x, Wih, Whh, bih, bhh, Wlin, blin, out);
}